// round 2
// baseline (speedup 1.0000x reference)
#include <cuda_runtime.h>

#define FULL 0xffffffffu
#define WPB 4            // warps (rays) per block
#define HN 64
#define LVL 4
#define SN 64

__global__ __launch_bounds__(128)
void mr_kernel(const float* __restrict__ rays_o,
               const float* __restrict__ rays_d,
               const float* __restrict__ levels,
               const float* __restrict__ W1,
               const float* __restrict__ b1,
               const float* __restrict__ W2,
               const float* __restrict__ b2,
               float* __restrict__ out,
               int N, int do_mask)
{
    __shared__ float4 sPack[HN];        // (W1[0][j], W1[1][j], W1[2][j], b1[j])
    __shared__ float  sW2[HN];
    __shared__ float  slev[LVL];
    __shared__ float  sscal[WPB][SN];

    int tid = threadIdx.x;
    if (tid < HN) {
        sPack[tid] = make_float4(W1[tid], W1[HN + tid], W1[2*HN + tid], b1[tid]);
        sW2[tid] = W2[tid];
    }
    if (tid < LVL) slev[tid] = levels[tid];
    __syncthreads();

    float addc = b2[0] + 1.0f;          // b2 + R0

    int lane = tid & 31;
    int warp = tid >> 5;
    int ray  = blockIdx.x * WPB + warp;
    if (ray >= N) return;

    float ox = rays_o[ray*3+0], oy = rays_o[ray*3+1], oz = rays_o[ray*3+2];
    float dx = rays_d[ray*3+0], dy = rays_d[ray*3+1], dz = rays_d[ray*3+2];

    // sphere bounds
    float bq = ox*dx + oy*dy + oz*dz;
    float cq = ox*ox + oy*oy + oz*oz - 9.0f;
    float disc = bq*bq - cq;
    bool  hit = disc > 0.0f;
    float sq = sqrtf(hit ? disc : 1.0f);
    float dnear = fmaxf(-bq - sq, 0.0f);
    float dfar  = fminf(-bq + sq, 100.0f);
    bool  mask_bound = hit && (dnear < dfar);

    float* scal = sscal[warp];

    // ---------------- Phase A: sample evals (2 per lane) ----------------
    unsigned vm0 = 0u, vm1 = 0u;
    float minv = 3.402823466e38f;
    int   minj = 0;                      // argmin over scal[s], s in [1,63] -> pair j = s-1
    #pragma unroll
    for (int half = 0; half < 2; ++half) {
        int s = lane + half*32;
        float t = (float)s / 63.0f;
        float dd = dnear*(1.0f - t) + dfar*t;
        float x0 = fmaf(dx, dd, ox);
        float x1 = fmaf(dy, dd, oy);
        float x2 = fmaf(dz, dd, oz);
        float acc = 0.0f;
        #pragma unroll 8
        for (int j = 0; j < HN; ++j) {
            float4 w = sPack[j];
            float pre = fmaf(x0, w.x, fmaf(x1, w.y, fmaf(x2, w.z, w.w)));
            acc = fmaf(tanhf(pre), sW2[j], acc);
        }
        float nrm = sqrtf(x0*x0 + x1*x1 + x2*x2);
        float sv = acc + addc - nrm;
        bool valid = nrm < 3.0f;
        scal[s] = sv;
        unsigned bal = __ballot_sync(FULL, valid);
        if (half == 0) vm0 = bal; else vm1 = bal;
        if (s >= 1 && sv < minv) { minv = sv; minj = s - 1; }
    }
    __syncwarp();

    // warp-reduce argmin (first occurrence on ties -> smaller index)
    #pragma unroll
    for (int off = 16; off >= 1; off >>= 1) {
        float ov = __shfl_xor_sync(FULL, minv, off);
        int   oj = __shfl_xor_sync(FULL, minj, off);
        if (ov < minv || (ov == minv && oj < minj)) { minv = ov; minj = oj; }
    }

    // ---------------- Phase B: interval search, 8 lanes per level ----------------
    int   mylev = lane & 3;
    int   grp   = lane >> 2;
    float lval  = slev[mylev];
    float brank = -3.402823466e38f;
    int   bj    = 63;
    int   anyi  = 0;
    #pragma unroll
    for (int k = 0; k < 8; ++k) {
        int j = grp*8 + k;
        if (j < 63) {
            float sf = scal[j], sb = scal[j+1];
            float diff = lval - sb;
            float sgn = (diff > 0.0f) ? 1.0f : ((diff < 0.0f) ? -1.0f : 0.0f);
            float rank = sgn * (float)(63 - j);
            if (rank > brank) { brank = rank; bj = j; }   // ascending j -> first max kept
            unsigned wv  = (j  < 32) ? vm0 : vm1;
            unsigned wv1 = (j+1 < 32) ? vm0 : vm1;
            bool vj  = (wv  >> (j & 31)) & 1u;
            bool vj1 = (wv1 >> ((j+1) & 31)) & 1u;
            if ((sf >= lval) && (lval >= sb) && vj && vj1) anyi = 1;
        }
    }
    // reduce across the 8 lanes sharing a level (xor 4,8,16 keeps lane&3 fixed)
    #pragma unroll
    for (int off = 4; off <= 16; off <<= 1) {
        float orank = __shfl_xor_sync(FULL, brank, off);
        int   obj   = __shfl_xor_sync(FULL, bj, off);
        int   oany  = __shfl_xor_sync(FULL, anyi, off);
        anyi |= oany;
        if (orank > brank || (orank == brank && obj < bj)) { brank = orank; bj = obj; }
    }
    int idxsel = anyi ? bj : minj;

    // ---------------- Phase C: secant (warp-collective evals), per level ----------------
    float dint[LVL];
    int   mint[LVL];
    #pragma unroll
    for (int lev = 0; lev < LVL; ++lev) {
        int   idx = __shfl_sync(FULL, idxsel, lev);   // lane 'lev' holds level 'lev'
        float lv  = slev[lev];
        float tF = (float)idx / 63.0f;
        float tB = (float)(idx+1) / 63.0f;
        float d_front = dnear*(1.0f - tF) + dfar*tF;
        float d_back  = dnear*(1.0f - tB) + dfar*tB;
        float s_front = scal[idx], s_back = scal[idx+1];
        bool  m_int = (s_front >= lv) && (lv >= s_back);
        float sdiff = s_front - s_back;
        bool  mvd = fabsf(sdiff) > 1e-4f;
        bool  m_sec = m_int && mvd;
        float d_sec = ((lv - s_back)*d_front + (s_front - lv)*d_back) / (mvd ? sdiff : 1.0f);
        float d_init = m_sec ? d_sec : d_back;

        float dfs = d_front, dbs = d_back, sfs = s_front, sbs = s_back, dcur = d_init;
        #pragma unroll
        for (int it = 0; it < 4; ++it) {
            float x0 = fmaf(dx, dcur, ox);
            float x1 = fmaf(dy, dcur, oy);
            float x2 = fmaf(dz, dcur, oz);
            float4 wA = sPack[lane];
            float4 wB = sPack[lane + 32];
            float preA = fmaf(x0, wA.x, fmaf(x1, wA.y, fmaf(x2, wA.z, wA.w)));
            float preB = fmaf(x0, wB.x, fmaf(x1, wB.y, fmaf(x2, wB.z, wB.w)));
            float part = tanhf(preA)*sW2[lane] + tanhf(preB)*sW2[lane + 32];
            #pragma unroll
            for (int off = 16; off >= 1; off >>= 1)
                part += __shfl_xor_sync(FULL, part, off);   // identical on all lanes
            float nrm = sqrtf(x0*x0 + x1*x1 + x2*x2);
            float s_mid = part + addc - nrm;
            bool mv = nrm < 3.0f;
            bool upf = (s_mid > lv) && mv;
            bool upb = (s_mid < lv) && mv;
            if (upf) { dfs = dcur; sfs = s_mid; }
            if (upb) { dbs = dcur; sbs = s_mid; }
            float sd = sfs - sbs;
            bool ok = fabsf(sd) > 1e-4f;
            float dn = ((lv - sbs)*dfs + (sfs - lv)*dbs) / (ok ? sd : 1.0f);
            dcur = ok ? dn : dcur;
        }
        dint[lev] = m_sec ? dcur : d_init;
        mint[lev] = m_int ? 1 : 0;
    }

    // ---------------- stable ascending sort of 4 (adjacent swaps, strict <) ----------------
    float d0 = dint[0], d1 = dint[1], d2 = dint[2], d3 = dint[3];
    int   m0 = mint[0], m1 = mint[1], m2 = mint[2], m3 = mint[3];
    #define CSW(da,ma,db,mb) do { if ((db) < (da)) { float _t=(da); (da)=(db); (db)=_t; int _m=(ma); (ma)=(mb); (mb)=_m; } } while(0)
    CSW(d0,m0,d1,m1); CSW(d1,m1,d2,m2); CSW(d2,m2,d3,m3);
    CSW(d0,m0,d1,m1); CSW(d1,m1,d2,m2);
    CSW(d0,m0,d1,m1);
    #undef CSW

    if (lane == 0) {
        float4 dv = mask_bound ? make_float4(d0, d1, d2, d3)
                               : make_float4(0.f, 0.f, 0.f, 0.f);
        *reinterpret_cast<float4*>(out + (size_t)ray*4) = dv;
        if (do_mask) {
            float4 mv4 = mask_bound ? make_float4((float)m0, (float)m1, (float)m2, (float)m3)
                                    : make_float4(0.f, 0.f, 0.f, 0.f);
            *reinterpret_cast<float4*>(out + (size_t)N*4 + (size_t)ray*4) = mv4;
        }
    }
}

extern "C" void kernel_launch(void* const* d_in, const int* in_sizes, int n_in,
                              void* d_out, int out_size) {
    const float* rays_o = (const float*)d_in[0];
    const float* rays_d = (const float*)d_in[1];
    const float* levels = (const float*)d_in[2];
    const float* W1     = (const float*)d_in[3];
    const float* b1     = (const float*)d_in[4];
    const float* W2     = (const float*)d_in[5];
    const float* b2     = (const float*)d_in[6];
    int N = in_sizes[0] / 3;
    int do_mask = (out_size >= 2 * N * LVL) ? 1 : 0;
    int blocks = (N + WPB - 1) / WPB;
    mr_kernel<<<blocks, 128>>>(rays_o, rays_d, levels, W1, b1, W2, b2,
                               (float*)d_out, N, do_mask);
}

// round 3
// speedup vs baseline: 1.0535x; 1.0535x over previous
#include <cuda_runtime.h>

#define FULL 0xffffffffu
#define WPB 4            // warps (rays) per block
#define HN 64
#define LVL 4
#define SN 64

__global__ __launch_bounds__(128)
void mr_kernel(const float* __restrict__ rays_o,
               const float* __restrict__ rays_d,
               const float* __restrict__ levels,
               const float* __restrict__ W1,
               const float* __restrict__ b1,
               const float* __restrict__ W2,
               const float* __restrict__ b2,
               float* __restrict__ out,
               int N, int do_mask)
{
    __shared__ float4 sPack[HN];        // (W1[0][j], W1[1][j], W1[2][j], b1[j])
    __shared__ float  sW2[HN];
    __shared__ float  slev[LVL];
    __shared__ float  sscal[WPB][SN];

    int tid = threadIdx.x;
    if (tid < HN) {
        sPack[tid] = make_float4(W1[tid], W1[HN + tid], W1[2*HN + tid], b1[tid]);
        sW2[tid] = W2[tid];
    }
    if (tid < LVL) slev[tid] = levels[tid];
    __syncthreads();

    float addc = b2[0] + 1.0f;          // b2 + R0

    int lane = tid & 31;
    int warp = tid >> 5;
    int ray  = blockIdx.x * WPB + warp;
    if (ray >= N) return;

    float ox = rays_o[ray*3+0], oy = rays_o[ray*3+1], oz = rays_o[ray*3+2];
    float dx = rays_d[ray*3+0], dy = rays_d[ray*3+1], dz = rays_d[ray*3+2];

    // sphere bounds
    float bq = ox*dx + oy*dy + oz*dz;
    float cq = ox*ox + oy*oy + oz*oz - 9.0f;
    float disc = bq*bq - cq;
    bool  hit = disc > 0.0f;
    float sq = sqrtf(hit ? disc : 1.0f);
    float dnear = fmaxf(-bq - sq, 0.0f);
    float dfar  = fminf(-bq + sq, 100.0f);
    bool  mask_bound = hit && (dnear < dfar);

    float* scal = sscal[warp];

    // ---------------- Phase A: sample evals (2 per lane) ----------------
    unsigned vm0 = 0u, vm1 = 0u;
    float minv = 3.402823466e38f;
    int   minj = 0;                      // argmin over scal[s], s in [1,63] -> pair j = s-1
    #pragma unroll
    for (int half = 0; half < 2; ++half) {
        int s = lane + half*32;
        float t = (float)s / 63.0f;
        float dd = dnear*(1.0f - t) + dfar*t;
        float x0 = fmaf(dx, dd, ox);
        float x1 = fmaf(dy, dd, oy);
        float x2 = fmaf(dz, dd, oz);
        float acc = 0.0f;
        #pragma unroll 8
        for (int j = 0; j < HN; ++j) {
            float4 w = sPack[j];
            float pre = fmaf(x0, w.x, fmaf(x1, w.y, fmaf(x2, w.z, w.w)));
            acc = fmaf(tanhf(pre), sW2[j], acc);
        }
        float nrm = sqrtf(x0*x0 + x1*x1 + x2*x2);
        float sv = acc + addc - nrm;
        bool valid = nrm < 3.0f;
        scal[s] = sv;
        unsigned bal = __ballot_sync(FULL, valid);
        if (half == 0) vm0 = bal; else vm1 = bal;
        if (s >= 1 && sv < minv) { minv = sv; minj = s - 1; }
    }
    __syncwarp();

    // warp-reduce argmin (first occurrence on ties -> smaller index)
    #pragma unroll
    for (int off = 16; off >= 1; off >>= 1) {
        float ov = __shfl_xor_sync(FULL, minv, off);
        int   oj = __shfl_xor_sync(FULL, minj, off);
        if (ov < minv || (ov == minv && oj < minj)) { minv = ov; minj = oj; }
    }

    // ---------------- Phase B: interval search, 8 lanes per level ----------------
    int   mylev = lane & 3;
    int   grp   = lane >> 2;
    float lval  = slev[mylev];
    float brank = -3.402823466e38f;
    int   bj    = 63;
    int   anyi  = 0;
    #pragma unroll
    for (int k = 0; k < 8; ++k) {
        int j = grp*8 + k;
        if (j < 63) {
            float sf = scal[j], sb = scal[j+1];
            float diff = lval - sb;
            float sgn = (diff > 0.0f) ? 1.0f : ((diff < 0.0f) ? -1.0f : 0.0f);
            float rank = sgn * (float)(63 - j);
            if (rank > brank) { brank = rank; bj = j; }   // ascending j -> first max kept
            unsigned wv  = (j  < 32) ? vm0 : vm1;
            unsigned wv1 = (j+1 < 32) ? vm0 : vm1;
            bool vj  = (wv  >> (j & 31)) & 1u;
            bool vj1 = (wv1 >> ((j+1) & 31)) & 1u;
            if ((sf >= lval) && (lval >= sb) && vj && vj1) anyi = 1;
        }
    }
    // reduce across the 8 lanes sharing a level (xor 4,8,16 keeps lane&3 fixed)
    #pragma unroll
    for (int off = 4; off <= 16; off <<= 1) {
        float orank = __shfl_xor_sync(FULL, brank, off);
        int   obj   = __shfl_xor_sync(FULL, bj, off);
        int   oany  = __shfl_xor_sync(FULL, anyi, off);
        anyi |= oany;
        if (orank > brank || (orank == brank && obj < bj)) { brank = orank; bj = obj; }
    }
    int idxsel = anyi ? bj : minj;

    // ---------------- Phase C: secant (warp-collective evals), per level ----------------
    float dint[LVL];
    int   mint[LVL];
    #pragma unroll
    for (int lev = 0; lev < LVL; ++lev) {
        int   idx = __shfl_sync(FULL, idxsel, lev);   // lane 'lev' holds level 'lev'
        float lv  = slev[lev];
        float tF = (float)idx / 63.0f;
        float tB = (float)(idx+1) / 63.0f;
        float d_front = dnear*(1.0f - tF) + dfar*tF;
        float d_back  = dnear*(1.0f - tB) + dfar*tB;
        float s_front = scal[idx], s_back = scal[idx+1];
        bool  m_int = (s_front >= lv) && (lv >= s_back);
        float sdiff = s_front - s_back;
        bool  mvd = fabsf(sdiff) > 1e-4f;
        bool  m_sec = m_int && mvd;
        float d_sec = ((lv - s_back)*d_front + (s_front - lv)*d_back) / (mvd ? sdiff : 1.0f);
        float d_init = m_sec ? d_sec : d_back;

        float dfs = d_front, dbs = d_back, sfs = s_front, sbs = s_back, dcur = d_init;
        #pragma unroll
        for (int it = 0; it < 4; ++it) {
            float x0 = fmaf(dx, dcur, ox);
            float x1 = fmaf(dy, dcur, oy);
            float x2 = fmaf(dz, dcur, oz);
            float4 wA = sPack[lane];
            float4 wB = sPack[lane + 32];
            float preA = fmaf(x0, wA.x, fmaf(x1, wA.y, fmaf(x2, wA.z, wA.w)));
            float preB = fmaf(x0, wB.x, fmaf(x1, wB.y, fmaf(x2, wB.z, wB.w)));
            float part = tanhf(preA)*sW2[lane] + tanhf(preB)*sW2[lane + 32];
            #pragma unroll
            for (int off = 16; off >= 1; off >>= 1)
                part += __shfl_xor_sync(FULL, part, off);   // identical on all lanes
            float nrm = sqrtf(x0*x0 + x1*x1 + x2*x2);
            float s_mid = part + addc - nrm;
            bool mv = nrm < 3.0f;
            bool upf = (s_mid > lv) && mv;
            bool upb = (s_mid < lv) && mv;
            if (upf) { dfs = dcur; sfs = s_mid; }
            if (upb) { dbs = dcur; sbs = s_mid; }
            float sd = sfs - sbs;
            bool ok = fabsf(sd) > 1e-4f;
            float dn = ((lv - sbs)*dfs + (sfs - lv)*dbs) / (ok ? sd : 1.0f);
            dcur = ok ? dn : dcur;
        }
        dint[lev] = m_sec ? dcur : d_init;
        mint[lev] = m_int ? 1 : 0;
    }

    // ---------------- stable ascending sort of 4 (adjacent swaps, strict <) ----------------
    float d0 = dint[0], d1 = dint[1], d2 = dint[2], d3 = dint[3];
    int   m0 = mint[0], m1 = mint[1], m2 = mint[2], m3 = mint[3];
    #define CSW(da,ma,db,mb) do { if ((db) < (da)) { float _t=(da); (da)=(db); (db)=_t; int _m=(ma); (ma)=(mb); (mb)=_m; } } while(0)
    CSW(d0,m0,d1,m1); CSW(d1,m1,d2,m2); CSW(d2,m2,d3,m3);
    CSW(d0,m0,d1,m1); CSW(d1,m1,d2,m2);
    CSW(d0,m0,d1,m1);
    #undef CSW

    if (lane == 0) {
        float4 dv = mask_bound ? make_float4(d0, d1, d2, d3)
                               : make_float4(0.f, 0.f, 0.f, 0.f);
        *reinterpret_cast<float4*>(out + (size_t)ray*4) = dv;
        if (do_mask) {
            float4 mv4 = mask_bound ? make_float4((float)m0, (float)m1, (float)m2, (float)m3)
                                    : make_float4(0.f, 0.f, 0.f, 0.f);
            *reinterpret_cast<float4*>(out + (size_t)N*4 + (size_t)ray*4) = mv4;
        }
    }
}

extern "C" void kernel_launch(void* const* d_in, const int* in_sizes, int n_in,
                              void* d_out, int out_size) {
    const float* rays_o = (const float*)d_in[0];
    const float* rays_d = (const float*)d_in[1];
    const float* levels = (const float*)d_in[2];
    const float* W1     = (const float*)d_in[3];
    const float* b1     = (const float*)d_in[4];
    const float* W2     = (const float*)d_in[5];
    const float* b2     = (const float*)d_in[6];
    int N = in_sizes[0] / 3;
    int do_mask = (out_size >= 2 * N * LVL) ? 1 : 0;
    int blocks = (N + WPB - 1) / WPB;
    mr_kernel<<<blocks, 128>>>(rays_o, rays_d, levels, W1, b1, W2, b2,
                               (float*)d_out, N, do_mask);
}